// round 1
// baseline (speedup 1.0000x reference)
#include <cuda_runtime.h>
#include <cstdint>
#include <cstddef>

#define N_NODE 100000
#define NTOT   102000
#define NFEAT  256
#define NDIM   128

// ---------------------------------------------------------------------------
// GEMM: x1[NTOT, 128] = concat(emb_node, emb_attri)[NTOT, 256] @ W1[128,256]^T
// Classic 128x128 tile SGEMM, BK=32, 256 threads, 8x8 per-thread microtile.
// ---------------------------------------------------------------------------
__global__ __launch_bounds__(256, 2) void gemm_x1_kernel(
    const float* __restrict__ emb_node,
    const float* __restrict__ emb_attri,
    const float* __restrict__ W1,
    float* __restrict__ x1)
{
    __shared__ float As[32][129];   // [k][m], padded to kill store conflicts
    __shared__ float Bs[32][129];   // [k][n]

    const int tid = threadIdx.x;
    const int m0  = blockIdx.x * 128;
    const int tr  = tid >> 4;   // 0..15 (row group of 8)
    const int tc  = tid & 15;   // 0..15 (col group of 8)

    float acc[8][8];
#pragma unroll
    for (int i = 0; i < 8; i++)
#pragma unroll
        for (int j = 0; j < 8; j++) acc[i][j] = 0.f;

    for (int k0 = 0; k0 < NFEAT; k0 += 32) {
        // Load A tile: 128 rows x 32 k-cols (transposed into As[k][m])
#pragma unroll
        for (int i = 0; i < 4; i++) {
            int idx = tid + i * 256;       // 0..1023 float4 slots
            int r   = idx >> 3;            // row in tile
            int c4  = idx & 7;             // float4 column
            int gr  = m0 + r;
            float4 v = make_float4(0.f, 0.f, 0.f, 0.f);
            if (gr < NTOT) {
                const float* src = (gr < N_NODE)
                    ? (emb_node + (size_t)gr * NFEAT)
                    : (emb_attri + (size_t)(gr - N_NODE) * NFEAT);
                v = __ldg((const float4*)(src + k0) + c4);
            }
            As[c4 * 4 + 0][r] = v.x;
            As[c4 * 4 + 1][r] = v.y;
            As[c4 * 4 + 2][r] = v.z;
            As[c4 * 4 + 3][r] = v.w;
        }
        // Load B tile: W1[j, k0:k0+32] -> Bs[k][j], j = 0..127
#pragma unroll
        for (int i = 0; i < 4; i++) {
            int idx = tid + i * 256;
            int j   = idx >> 3;
            int c4  = idx & 7;
            float4 v = __ldg((const float4*)(W1 + (size_t)j * NFEAT + k0) + c4);
            Bs[c4 * 4 + 0][j] = v.x;
            Bs[c4 * 4 + 1][j] = v.y;
            Bs[c4 * 4 + 2][j] = v.z;
            Bs[c4 * 4 + 3][j] = v.w;
        }
        __syncthreads();

#pragma unroll
        for (int kk = 0; kk < 32; kk++) {
            float ra[8], rb[8];
#pragma unroll
            for (int i = 0; i < 8; i++) ra[i] = As[kk][tr * 8 + i];
#pragma unroll
            for (int j = 0; j < 8; j++) rb[j] = Bs[kk][tc * 8 + j];
#pragma unroll
            for (int i = 0; i < 8; i++)
#pragma unroll
                for (int j = 0; j < 8; j++)
                    acc[i][j] = fmaf(ra[i], rb[j], acc[i][j]);
        }
        __syncthreads();
    }

#pragma unroll
    for (int i = 0; i < 8; i++) {
        int gr = m0 + tr * 8 + i;
        if (gr < NTOT) {
            float4* dst = (float4*)(x1 + (size_t)gr * NDIM + tc * 8);
            dst[0] = make_float4(acc[i][0], acc[i][1], acc[i][2], acc[i][3]);
            dst[1] = make_float4(acc[i][4], acc[i][5], acc[i][6], acc[i][7]);
        }
    }
}

// ---------------------------------------------------------------------------
// SpMM scatter: out[row[e], :] += val[e] * x1[col[e], :]
// One warp per edge: lane l handles floats [4l, 4l+4). Gather is a coalesced
// 512B warp read (L2-resident: x1 = 52MB < L2). Scatter uses vectorized
// red.global.add.v4.f32 (1 LTS op per 16B instead of 4).
// ---------------------------------------------------------------------------
__global__ __launch_bounds__(256) void spmm_kernel(
    const int*   __restrict__ row,
    const int*   __restrict__ col,
    const float* __restrict__ val,
    const float* __restrict__ x1,
    float*       __restrict__ out,
    int nedges)
{
    const int warp = (int)((blockIdx.x * (unsigned)blockDim.x + threadIdx.x) >> 5);
    const int lane = threadIdx.x & 31;
    if (warp >= nedges) return;

    const int   r = __ldg(row + warp);
    const int   c = __ldg(col + warp);
    const float v = __ldg(val + warp);

    float4 x = __ldg((const float4*)(x1 + (size_t)c * NDIM) + lane);
    float4 y;
    y.x = x.x * v; y.y = x.y * v; y.z = x.z * v; y.w = x.w * v;

    float* dst = out + (size_t)r * NDIM + lane * 4;
    asm volatile("red.global.add.v4.f32 [%0], {%1, %2, %3, %4};"
                 :: "l"(dst), "f"(y.x), "f"(y.y), "f"(y.z), "f"(y.w)
                 : "memory");
}

// ---------------------------------------------------------------------------
// Launch
// ---------------------------------------------------------------------------
extern "C" void kernel_launch(void* const* d_in, const int* in_sizes, int n_in,
                              void* d_out, int out_size)
{
    const float* emb_node  = (const float*)d_in[0];
    const float* emb_attri = (const float*)d_in[1];
    const float* W1        = (const float*)d_in[2];
    const int*   adj_row   = (const int*)d_in[3];
    const int*   adj_col   = (const int*)d_in[4];
    const float* adj_val   = (const float*)d_in[5];
    const int*   adj2_row  = (const int*)d_in[6];
    const int*   adj2_col  = (const int*)d_in[7];
    const float* adj2_val  = (const float*)d_in[8];

    const int E1 = in_sizes[3];
    const int E2 = in_sizes[6];

    float* out = (float*)d_out;
    float* x1 = out;                                 // [NTOT, 128]
    float* x2 = out + (size_t)NTOT * NDIM;           // [NTOT, 128]
    float* x3 = out + (size_t)2 * NTOT * NDIM;       // [NTOT, 128]

    // Zero the scatter-add targets (d_out is poisoned by the harness).
    cudaMemsetAsync(x2, 0, (size_t)2 * NTOT * NDIM * sizeof(float));

    // x1 = x0 @ W1^T
    int gemm_blocks = (NTOT + 127) / 128;            // 797
    gemm_x1_kernel<<<gemm_blocks, 256>>>(emb_node, emb_attri, W1, x1);

    // x2 = spmm(adj, x1); x3 = spmm(adj2, x1)
    int blocks1 = (int)(((long long)E1 * 32 + 255) / 256);
    int blocks2 = (int)(((long long)E2 * 32 + 255) / 256);
    spmm_kernel<<<blocks1, 256>>>(adj_row, adj_col, adj_val, x1, x2, E1);
    spmm_kernel<<<blocks2, 256>>>(adj2_row, adj2_col, adj2_val, x1, x3, E2);
}